// round 14
// baseline (speedup 1.0000x reference)
#include <cuda_runtime.h>
#include <math.h>

// Problem constants (fixed shapes)
#define BATCH 4
#define TLEN  1024
#define CH    512
#define DH    16
#define NROWS (BATCH*TLEN)   // 4096
#define OUTS  48             // k(16) | v(16) | r(16)
#define OCH   64
#define NSPL  8              // effective K-splits (4 block-splits x 2 halves)
#define NBLOCKS 148
#define NTHREADS 512

typedef unsigned long long ull;
typedef unsigned int uint;

// Scratch (device globals)
__device__ float g_pk[NSPL*DH*NROWS];
__device__ float g_pv[NSPL*DH*NROWS];
__device__ float g_pr[NSPL*DH*NROWS];
__device__ float g_rwkvT[DH*NROWS];       // [d][row]
__device__ float g_wsum[TLEN];
// Fast-barrier state: one flag per block on its own 128B line + go words.
__device__ uint g_flag[2][NBLOCKS*32];
__device__ uint g_go[2];

__device__ __forceinline__ void ffma2(ull& acc, ull a, ull b) {
    asm("fma.rn.f32x2 %0, %1, %2, %0;" : "+l"(acc) : "l"(a), "l"(b));
}
__device__ __forceinline__ ull dup2(uint w) {
    ull r; asm("mov.b64 %0, {%1, %1};" : "=l"(r) : "r"(w)); return r;
}

// Replay-safe fast grid barrier: distributed flag arrival (parallel STGs),
// block 0 aggregates with 148 parallel pollers, broadcast release via g_go.
__shared__ uint s_bar_epoch;
__device__ __forceinline__ void grid_barrier(int id, int bid, int tid) {
    __syncthreads();
    if (tid == 0) {
        __threadfence();
        uint e = g_flag[id][bid * 32] + 1u;
        *(volatile uint*)&g_flag[id][bid * 32] = e;
        s_bar_epoch = e;
    }
    __syncthreads();
    uint e = s_bar_epoch;
    if (bid == 0) {
        if (tid < NBLOCKS) {
            volatile uint* p = &g_flag[id][tid * 32];
            while ((int)(*p - e) < 0) { }
        }
        __syncthreads();
        if (tid == 0) {
            __threadfence();
            *(volatile uint*)&g_go[id] = e;
        }
        __syncthreads();
    } else {
        if (tid == 0) {
            volatile uint* p = &g_go[id];
            while ((int)(*p - e) < 0) { }
            __threadfence();
        }
        __syncthreads();
    }
}

// Dynamic shared memory (90 KB, overlaid across phases)
struct ProjSmem {
    float2 Xp[2][64][65];     // [half][kk][pair+pad]  66560 B
    float  Ws[2][64][50];     // [half][kk][out+pad]   25600 B
};
#define SMEM_BYTES sizeof(ProjSmem)
struct ScanSmem { float wsh[16]; float rsh[16]; float km; };
// wsum blocks overlay: float s_twr[1024]; float s_beta[1024];  (8 KB)

extern __shared__ __align__(16) char s_raw[];

__global__ __launch_bounds__(NTHREADS) void rwkv_persistent(
    const float* __restrict__ x,
    const float* __restrict__ time_w,
    const float* __restrict__ alpha,
    const float* __restrict__ beta,
    const float* __restrict__ gamma,
    const float* __restrict__ Wk, const float* __restrict__ bk,
    const float* __restrict__ Wv, const float* __restrict__ bv,
    const float* __restrict__ Wr, const float* __restrict__ br,
    const float* __restrict__ Wo, const float* __restrict__ bo,
    float* __restrict__ out)
{
    int bid = blockIdx.x;
    int tid = threadIdx.x;

    // ======================= PHASE A =======================
    if (bid < 128) {
        // ---- projection partial GEMM (single KC=64 stage) ----
        ProjSmem* S = (ProjSmem*)s_raw;
        int tile  = bid >> 2;            // 0..31
        int split = bid & 3;             // 0..3
        int row0  = tile * 128;
        int half  = tid >> 8;            // 0..1 : K sub-chunk (64 wide)
        int ht    = tid & 255;
        int rx    = ht & 31;             // pairs rx, rx+32
        int oy    = ht >> 5;             // 0..7
        int o0    = oy * 6;
        int kc    = split * 128 + half * 64;
        bool shifted = (kc < CH/2);      // 64-chunks never straddle 256

        ull acc[6][2];
        #pragma unroll
        for (int j = 0; j < 6; j++) { acc[j][0] = 0ull; acc[j][1] = 0ull; }

        // stage weights: Ws[half][kk][out] (48x64 floats per half, 256 thr)
        #pragma unroll
        for (int it = 0; it < 12; it++) {
            int e  = ht + it * 256;
            int kk = e & 63;
            int o  = e >> 6;        // 0..47
            const float* wsrc = (o < 16) ? (Wk + o * CH)
                              : (o < 32) ? (Wv + (o - 16) * CH)
                                         : (Wr + (o - 32) * CH);
            S->Ws[half][kk][o] = wsrc[kc + kk];
        }
        // stage x pairs with time shift: Xp[half][kk][rp] (64x64 per half)
        #pragma unroll
        for (int it = 0; it < 16; it++) {
            int e  = ht + it * 256;
            int kk = e & 63;
            int rp = e >> 6;        // 0..63
            int c  = kc + kk;
            int row = row0 + rp * 2;
            float v0, v1;
            if (shifted) {
                int t0 = row & (TLEN - 1);
                v0 = t0 ? x[(row - 1) * CH + c] : 0.f;
                v1 = x[row * CH + c];
            } else {
                v0 = x[row * CH + c];
                v1 = x[(row + 1) * CH + c];
            }
            S->Xp[half][kk][rp] = make_float2(v0, v1);
        }
        __syncthreads();

        #pragma unroll 8
        for (int kk = 0; kk < 64; kk++) {
            ull xv0 = *(const ull*)&S->Xp[half][kk][rx];
            ull xv1 = *(const ull*)&S->Xp[half][kk][rx + 32];
            uint2 w01 = *(const uint2*)&S->Ws[half][kk][o0];
            uint2 w23 = *(const uint2*)&S->Ws[half][kk][o0 + 2];
            uint2 w45 = *(const uint2*)&S->Ws[half][kk][o0 + 4];
            ull wp[6];
            wp[0] = dup2(w01.x); wp[1] = dup2(w01.y);
            wp[2] = dup2(w23.x); wp[3] = dup2(w23.y);
            wp[4] = dup2(w45.x); wp[5] = dup2(w45.y);
            #pragma unroll
            for (int j = 0; j < 6; j++) {
                ffma2(acc[j][0], wp[j], xv0);
                ffma2(acc[j][1], wp[j], xv1);
            }
        }

        // epilogue: raw partials [s][d][row], s = split*2+half
        int s = split * 2 + half;
        #pragma unroll
        for (int j = 0; j < 6; j++) {
            int o     = o0 + j;
            int d     = o & 15;
            int which = o >> 4;
            float* dst = (which == 0) ? g_pk : (which == 1) ? g_pv : g_pr;
            dst += (s * DH + d) * NROWS;
            #pragma unroll
            for (int i = 0; i < 2; i++) {
                float2 a = *(float2*)&acc[j][i];
                *(float2*)&dst[row0 + (rx + 32 * i) * 2] = a;
            }
        }
    } else {
        // ---- wsum on blocks 128..147, smem-staged (LDS inner loop) ----
        float* s_twr  = (float*)s_raw;          // [1024] time_w reversed
        float* s_beta = ((float*)s_raw) + TLEN; // [1024]
        for (int i = tid; i < TLEN; i += NTHREADS) {
            s_twr[i]  = time_w[TLEN - 1 - i];
            s_beta[i] = beta[i];
        }
        __syncthreads();

        int wb   = bid - 128;           // 0..19
        int wid  = tid >> 5;            // 0..15
        int lane = tid & 31;
        for (int u = wb * 16 + wid; u < TLEN; u += 320) {
            float s = 0.f;
            int dmax = TLEN - 1 - u;
            #pragma unroll 4
            for (int d = lane; d <= dmax; d += 32)
                s += s_twr[d] * s_beta[u + d];
            #pragma unroll
            for (int off = 16; off > 0; off >>= 1)
                s += __shfl_down_sync(0xFFFFFFFFu, s, off);
            if (lane == 0) g_wsum[u] = alpha[u] * s;
        }
    }

    grid_barrier(0, bid, tid);

    // ======================= PHASE B : scan (blocks 0..63) =======================
    if (bid < BATCH * DH) {
        ScanSmem* S = (ScanSmem*)s_raw;
        int b = bid >> 4;
        int d = bid & 15;
        int lane = tid & 31;
        int wid  = tid >> 5;            // 0..15
        int t0   = tid * 2;
        int base = d * NROWS + (b << 10) + t0;

        float2 ks = make_float2(0.f, 0.f);
        float2 vs = ks, rs = ks;
        #pragma unroll
        for (int s = 0; s < NSPL; s++) {
            int off = s * (DH * NROWS) + base;
            float2 a = *(const float2*)&g_pk[off];
            float2 c = *(const float2*)&g_pv[off];
            float2 e = *(const float2*)&g_pr[off];
            ks.x += a.x; ks.y += a.y;
            vs.x += c.x; vs.y += c.y;
            rs.x += e.x; rs.y += e.y;
        }
        float bkd = bk[d], bvd = bv[d], brd = br[d];
        float k0 = expf(fminf(fmaxf(ks.x + bkd, -60.f), 30.f));
        float k1 = expf(fminf(fmaxf(ks.y + bkd, -60.f), 30.f));
        float v0 = vs.x + bvd, v1 = vs.y + bvd;
        float r0 = rs.x + brd, r1 = rs.y + brd;

        // local inclusive prefix
        float p0 = k0, p1 = k0 + k1;
        float tot = p1;
        // warp inclusive scan of tot
        float sc = tot;
        #pragma unroll
        for (int off = 1; off < 32; off <<= 1) {
            float n = __shfl_up_sync(0xFFFFFFFFu, sc, off);
            if (lane >= off) sc += n;
        }
        if (lane == 31) S->wsh[wid] = sc;
        // kv reduction
        float kvs = k0 * v0 + k1 * v1;
        #pragma unroll
        for (int off = 16; off > 0; off >>= 1)
            kvs += __shfl_down_sync(0xFFFFFFFFu, kvs, off);
        if (lane == 0) S->rsh[wid] = kvs;
        __syncthreads();
        if (tid == 0) {
            float run = 0.f, kmacc = 0.f;
            #pragma unroll
            for (int w = 0; w < 16; w++) {
                float t = S->wsh[w]; S->wsh[w] = run; run += t;
                kmacc += S->rsh[w];
            }
            S->km = kmacc * (1.0f / (float)TLEN);
        }
        __syncthreads();
        float blk_excl = S->wsh[wid] + (sc - tot);
        float km = S->km;
        float2 wst = *(const float2*)&g_wsum[t0];

        float c0 = blk_excl + p0, c1 = blk_excl + p1;
        float2 o2;
        o2.x = r0 * wst.x * km * __fdividef(1.0f, c0 + 1e-8f);
        o2.y = r1 * wst.y * km * __fdividef(1.0f, c1 + 1e-8f);
        *(float2*)&g_rwkvT[base] = o2;
    }

    grid_barrier(1, bid, tid);

    // ======================= PHASE C : output GEMM =======================
    {
        int o  = tid & 63;
        int rl = tid >> 6;              // 0..7
        const float4* wop = (const float4*)(Wo + o * DH);
        float4 w0 = wop[0], w1 = wop[1], w2 = wop[2], w3 = wop[3];
        float wor[16] = {w0.x,w0.y,w0.z,w0.w, w1.x,w1.y,w1.z,w1.w,
                         w2.x,w2.y,w2.z,w2.w, w3.x,w3.y,w3.z,w3.w};
        float bov = bo[o];

        for (int g = bid; g < NROWS / 8; g += NBLOCKS) {
            int row = g * 8 + rl;
            int t   = row & (TLEN - 1);
            float acc = 0.f;
            #pragma unroll
            for (int d = 0; d < DH; d++)
                acc += __ldg(&g_rwkvT[d * NROWS + row]) * wor[d];
            out[row * OCH + o] = (acc + bov) * gamma[t];
        }
    }
}

// ---------------------------------------------------------------------------
extern "C" void kernel_launch(void* const* d_in, const int* in_sizes, int n_in,
                              void* d_out, int out_size)
{
    const float* x      = (const float*)d_in[0];
    const float* time_w = (const float*)d_in[1];
    const float* alpha  = (const float*)d_in[2];
    const float* beta   = (const float*)d_in[3];
    const float* gamma  = (const float*)d_in[4];
    const float* Wk     = (const float*)d_in[5];
    const float* bk     = (const float*)d_in[6];
    const float* Wv     = (const float*)d_in[7];
    const float* bv     = (const float*)d_in[8];
    const float* Wr     = (const float*)d_in[9];
    const float* br     = (const float*)d_in[10];
    const float* Wo     = (const float*)d_in[11];
    const float* bo     = (const float*)d_in[12];
    float* out = (float*)d_out;

    cudaFuncSetAttribute(rwkv_persistent,
                         cudaFuncAttributeMaxDynamicSharedMemorySize,
                         (int)SMEM_BYTES);
    rwkv_persistent<<<NBLOCKS, NTHREADS, SMEM_BYTES>>>(
        x, time_w, alpha, beta, gamma,
        Wk, bk, Wv, bv, Wr, br, Wo, bo, out);
}

// round 15
// speedup vs baseline: 1.0107x; 1.0107x over previous
#include <cuda_runtime.h>
#include <math.h>

// Problem constants (fixed shapes)
#define BATCH 4
#define TLEN  1024
#define CH    512
#define DH    16
#define NROWS (BATCH*TLEN)   // 4096
#define OUTS  48             // k(16) | v(16) | r(16)
#define OCH   64
#define NSPL  8              // effective K-splits (4 block-splits x 2 halves)
#define NBLOCKS 148
#define NTHREADS 512

typedef unsigned long long ull;
typedef unsigned int uint;

// Scratch (device globals)
__device__ float g_pk[NSPL*DH*NROWS];
__device__ float g_pv[NSPL*DH*NROWS];
__device__ float g_pr[NSPL*DH*NROWS];
__device__ float g_rwkvT[DH*NROWS];       // [d][row]
__device__ float g_wsum[TLEN];

// Producer->consumer flags (epoch counters, monotonic, replay-safe).
// Each on its own 128B line.
__device__ uint g_epoch_blk[NBLOCKS*32];  // per-block run counter
__device__ uint g_flagA[128*32];          // proj blocks done
__device__ uint g_flagW[20*32];           // wsum blocks done
__device__ uint g_flagS[64*32];           // scan blocks done

__device__ __forceinline__ void ffma2(ull& acc, ull a, ull b) {
    asm("fma.rn.f32x2 %0, %1, %2, %0;" : "+l"(acc) : "l"(a), "l"(b));
}
__device__ __forceinline__ ull dup2(uint w) {
    ull r; asm("mov.b64 %0, {%1, %1};" : "=l"(r) : "r"(w)); return r;
}
__device__ __forceinline__ void poll_ge(volatile uint* p, uint e) {
    while ((int)(*p - e) < 0) { }
}

// Shared memory (46080 B, overlaid across phases)
struct ProjSmem {
    float  Ws[2][32][50];     // [half][kk][out+pad]   12800 B
    float2 Xp[2][32][65];     // [half][kk][pair+pad]  33280 B
};
struct ScanSmem { float wsh[16]; float rsh[16]; float km; };
// wsum blocks overlay: float s_twr[1024]; float s_beta[1024];  (8 KB)

__global__ __launch_bounds__(NTHREADS) void rwkv_persistent(
    const float* __restrict__ x,
    const float* __restrict__ time_w,
    const float* __restrict__ alpha,
    const float* __restrict__ beta,
    const float* __restrict__ gamma,
    const float* __restrict__ Wk, const float* __restrict__ bk,
    const float* __restrict__ Wv, const float* __restrict__ bv,
    const float* __restrict__ Wr, const float* __restrict__ br,
    const float* __restrict__ Wo, const float* __restrict__ bo,
    float* __restrict__ out)
{
    __shared__ __align__(16) char s_raw[sizeof(ProjSmem)];
    __shared__ uint s_epoch;
    int bid = blockIdx.x;
    int tid = threadIdx.x;

    // per-run epoch (only this block writes its counter; monotonic)
    if (tid == 0) {
        uint e = *(volatile uint*)&g_epoch_blk[bid * 32] + 1u;
        *(volatile uint*)&g_epoch_blk[bid * 32] = e;
        s_epoch = e;
    }
    __syncthreads();
    uint e = s_epoch;

    // ======================= PHASE A =======================
    if (bid < 128) {
        // ---- projection partial GEMM ----
        ProjSmem* S = (ProjSmem*)s_raw;
        int tile  = bid >> 2;            // 0..31
        int split = bid & 3;             // 0..3
        int row0  = tile * 128;
        int half  = tid >> 8;            // 0..1 : K sub-chunk (64 wide)
        int ht    = tid & 255;
        int rx    = ht & 31;             // pairs rx, rx+32
        int oy    = ht >> 5;             // 0..7
        int o0    = oy * 6;
        int kbaseh = split * 128 + half * 64;
        bool shifted = (kbaseh < CH/2);  // 32-chunks never straddle 256

        ull acc[6][2];
        #pragma unroll
        for (int j = 0; j < 6; j++) { acc[j][0] = 0ull; acc[j][1] = 0ull; }

        for (int kt = 0; kt < 2; kt++) {
            int kc = kbaseh + kt * 32;

            // stage weights: Ws[half][kk][out] (48x32 floats per half, 256 thr)
            #pragma unroll
            for (int it = 0; it < 6; it++) {
                int e2 = ht + it * 256;
                int kk = e2 & 31;
                int o  = e2 >> 5;       // 0..47
                const float* wsrc = (o < 16) ? (Wk + o * CH)
                                  : (o < 32) ? (Wv + (o - 16) * CH)
                                             : (Wr + (o - 32) * CH);
                S->Ws[half][kk][o] = wsrc[kc + kk];
            }
            // stage x pairs with time shift: Xp[half][kk][rp] (64x32 per half)
            #pragma unroll
            for (int it = 0; it < 8; it++) {
                int e2 = ht + it * 256;
                int kk = e2 & 31;
                int rp = e2 >> 5;       // 0..63
                int c  = kc + kk;
                int row = row0 + rp * 2;
                float v0, v1;
                if (shifted) {
                    int t0 = row & (TLEN - 1);
                    v0 = t0 ? x[(row - 1) * CH + c] : 0.f;
                    v1 = x[row * CH + c];
                } else {
                    v0 = x[row * CH + c];
                    v1 = x[(row + 1) * CH + c];
                }
                S->Xp[half][kk][rp] = make_float2(v0, v1);
            }
            __syncthreads();

            #pragma unroll 8
            for (int kk = 0; kk < 32; kk++) {
                ull xv0 = *(const ull*)&S->Xp[half][kk][rx];
                ull xv1 = *(const ull*)&S->Xp[half][kk][rx + 32];
                uint2 w01 = *(const uint2*)&S->Ws[half][kk][o0];
                uint2 w23 = *(const uint2*)&S->Ws[half][kk][o0 + 2];
                uint2 w45 = *(const uint2*)&S->Ws[half][kk][o0 + 4];
                ull wp[6];
                wp[0] = dup2(w01.x); wp[1] = dup2(w01.y);
                wp[2] = dup2(w23.x); wp[3] = dup2(w23.y);
                wp[4] = dup2(w45.x); wp[5] = dup2(w45.y);
                #pragma unroll
                for (int j = 0; j < 6; j++) {
                    ffma2(acc[j][0], wp[j], xv0);
                    ffma2(acc[j][1], wp[j], xv1);
                }
            }
            __syncthreads();
        }

        // epilogue: raw partials [s][d][row], s = split*2+half
        int s = split * 2 + half;
        #pragma unroll
        for (int j = 0; j < 6; j++) {
            int o     = o0 + j;
            int d     = o & 15;
            int which = o >> 4;
            float* dst = (which == 0) ? g_pk : (which == 1) ? g_pv : g_pr;
            dst += (s * DH + d) * NROWS;
            #pragma unroll
            for (int i = 0; i < 2; i++) {
                float2 a = *(float2*)&acc[j][i];
                *(float2*)&dst[row0 + (rx + 32 * i) * 2] = a;
            }
        }
        // signal: this proj block's partials are visible
        __threadfence();
        __syncthreads();
        if (tid == 0) *(volatile uint*)&g_flagA[bid * 32] = e;
    } else {
        // ---- wsum on blocks 128..147, smem-staged (LDS inner loop) ----
        float* s_twr  = (float*)s_raw;          // [1024] time_w reversed
        float* s_beta = ((float*)s_raw) + TLEN; // [1024]
        for (int i = tid; i < TLEN; i += NTHREADS) {
            s_twr[i]  = time_w[TLEN - 1 - i];
            s_beta[i] = beta[i];
        }
        __syncthreads();

        int wb   = bid - 128;           // 0..19
        int wid  = tid >> 5;            // 0..15
        int lane = tid & 31;
        for (int u = wb * 16 + wid; u < TLEN; u += 320) {
            float s = 0.f;
            int dmax = TLEN - 1 - u;
            #pragma unroll 4
            for (int d = lane; d <= dmax; d += 32)
                s += s_twr[d] * s_beta[u + d];
            #pragma unroll
            for (int off = 16; off > 0; off >>= 1)
                s += __shfl_down_sync(0xFFFFFFFFu, s, off);
            if (lane == 0) g_wsum[u] = alpha[u] * s;
        }
        __threadfence();
        __syncthreads();
        if (tid == 0) *(volatile uint*)&g_flagW[wb * 32] = e;
    }

    // ======================= PHASE B : scan (blocks 0..63) =======================
    if (bid < BATCH * DH) {
        int b = bid >> 4;
        int d = bid & 15;

        // wait only for this batch's 32 proj producers + 20 wsum producers
        if (tid < 32) {
            poll_ge(&g_flagA[(32 * b + tid) * 32], e);
            __threadfence();
        } else if (tid < 52) {
            poll_ge(&g_flagW[(tid - 32) * 32], e);
            __threadfence();
        }
        __syncthreads();

        ScanSmem* S = (ScanSmem*)s_raw;
        int lane = tid & 31;
        int wid  = tid >> 5;            // 0..15
        int t0   = tid * 2;
        int base = d * NROWS + (b << 10) + t0;

        float2 ks = make_float2(0.f, 0.f);
        float2 vs = ks, rs = ks;
        #pragma unroll
        for (int s = 0; s < NSPL; s++) {
            int off = s * (DH * NROWS) + base;
            float2 a = *(const float2*)&g_pk[off];
            float2 c = *(const float2*)&g_pv[off];
            float2 e2 = *(const float2*)&g_pr[off];
            ks.x += a.x; ks.y += a.y;
            vs.x += c.x; vs.y += c.y;
            rs.x += e2.x; rs.y += e2.y;
        }
        float bkd = bk[d], bvd = bv[d], brd = br[d];
        float k0 = expf(fminf(fmaxf(ks.x + bkd, -60.f), 30.f));
        float k1 = expf(fminf(fmaxf(ks.y + bkd, -60.f), 30.f));
        float v0 = vs.x + bvd, v1 = vs.y + bvd;
        float r0 = rs.x + brd, r1 = rs.y + brd;

        // local inclusive prefix
        float p0 = k0, p1 = k0 + k1;
        float tot = p1;
        // warp inclusive scan of tot
        float sc = tot;
        #pragma unroll
        for (int off = 1; off < 32; off <<= 1) {
            float n = __shfl_up_sync(0xFFFFFFFFu, sc, off);
            if (lane >= off) sc += n;
        }
        if (lane == 31) S->wsh[wid] = sc;
        // kv reduction
        float kvs = k0 * v0 + k1 * v1;
        #pragma unroll
        for (int off = 16; off > 0; off >>= 1)
            kvs += __shfl_down_sync(0xFFFFFFFFu, kvs, off);
        if (lane == 0) S->rsh[wid] = kvs;
        __syncthreads();
        if (tid == 0) {
            float run = 0.f, kmacc = 0.f;
            #pragma unroll
            for (int w = 0; w < 16; w++) {
                float t = S->wsh[w]; S->wsh[w] = run; run += t;
                kmacc += S->rsh[w];
            }
            S->km = kmacc * (1.0f / (float)TLEN);
        }
        __syncthreads();
        float blk_excl = S->wsh[wid] + (sc - tot);
        float km = S->km;
        float2 wst = *(const float2*)&g_wsum[t0];

        float c0 = blk_excl + p0, c1 = blk_excl + p1;
        float2 o2;
        o2.x = r0 * wst.x * km * __fdividef(1.0f, c0 + 1e-8f);
        o2.y = r1 * wst.y * km * __fdividef(1.0f, c1 + 1e-8f);
        *(float2*)&g_rwkvT[base] = o2;

        __threadfence();
        __syncthreads();
        if (tid == 0) *(volatile uint*)&g_flagS[bid * 32] = e;
    }

    // ======================= PHASE C : output GEMM =======================
    {
        // wait for all 64 scan blocks
        if (tid < 64) {
            poll_ge(&g_flagS[tid * 32], e);
            __threadfence();
        }
        __syncthreads();

        int o  = tid & 63;
        int rl = tid >> 6;              // 0..7
        const float4* wop = (const float4*)(Wo + o * DH);
        float4 w0 = wop[0], w1 = wop[1], w2 = wop[2], w3 = wop[3];
        float wor[16] = {w0.x,w0.y,w0.z,w0.w, w1.x,w1.y,w1.z,w1.w,
                         w2.x,w2.y,w2.z,w2.w, w3.x,w3.y,w3.z,w3.w};
        float bov = bo[o];

        for (int g = bid; g < NROWS / 8; g += NBLOCKS) {
            int row = g * 8 + rl;
            int t   = row & (TLEN - 1);
            float acc = 0.f;
            #pragma unroll
            for (int d = 0; d < DH; d++)
                acc += __ldg(&g_rwkvT[d * NROWS + row]) * wor[d];
            out[row * OCH + o] = (acc + bov) * gamma[t];
        }
    }
}

// ---------------------------------------------------------------------------
extern "C" void kernel_launch(void* const* d_in, const int* in_sizes, int n_in,
                              void* d_out, int out_size)
{
    const float* x      = (const float*)d_in[0];
    const float* time_w = (const float*)d_in[1];
    const float* alpha  = (const float*)d_in[2];
    const float* beta   = (const float*)d_in[3];
    const float* gamma  = (const float*)d_in[4];
    const float* Wk     = (const float*)d_in[5];
    const float* bk     = (const float*)d_in[6];
    const float* Wv     = (const float*)d_in[7];
    const float* bv     = (const float*)d_in[8];
    const float* Wr     = (const float*)d_in[9];
    const float* br     = (const float*)d_in[10];
    const float* Wo     = (const float*)d_in[11];
    const float* bo     = (const float*)d_in[12];
    float* out = (float*)d_out;

    rwkv_persistent<<<NBLOCKS, NTHREADS>>>(
        x, time_w, alpha, beta, gamma,
        Wk, bk, Wv, bv, Wr, br, Wo, bo, out);
}

// round 16
// speedup vs baseline: 1.1068x; 1.0952x over previous
#include <cuda_runtime.h>
#include <math.h>

// Problem constants (fixed shapes)
#define BATCH 4
#define TLEN  1024
#define CH    512
#define DH    16
#define NROWS (BATCH*TLEN)   // 4096
#define OUTS  48             // k(16) | v(16) | r(16)
#define OCH   64
#define NSPL  4              // K-splits after in-block half merge
#define NBLOCKS 148
#define NTHREADS 512

typedef unsigned long long ull;
typedef unsigned int uint;

// Scratch (device globals)
__device__ float g_pk[NSPL*DH*NROWS];
__device__ float g_pv[NSPL*DH*NROWS];
__device__ float g_pr[NSPL*DH*NROWS];
__device__ float g_rwkvT[DH*NROWS];       // [d][row]
__device__ float g_wsum[TLEN];
__device__ unsigned int g_barcnt[2];      // monotonic barrier counters

__device__ __forceinline__ void ffma2(ull& acc, ull a, ull b) {
    asm("fma.rn.f32x2 %0, %1, %2, %0;" : "+l"(acc) : "l"(a), "l"(b));
}
__device__ __forceinline__ ull dup2(uint w) {
    ull r; asm("mov.b64 %0, {%1, %1};" : "=l"(r) : "r"(w)); return r;
}

// Replay-safe grid barrier (monotonic counter, wrap-safe compare).
__device__ __forceinline__ void grid_barrier(int id) {
    __syncthreads();
    if (threadIdx.x == 0) {
        __threadfence();
        unsigned int ticket = atomicAdd(&g_barcnt[id], 1u);
        unsigned int target = (ticket / NBLOCKS + 1u) * NBLOCKS;
        volatile unsigned int* p = &g_barcnt[id];
        while ((int)(*p - target) < 0) { }
        __threadfence();
    }
    __syncthreads();
}

// Shared memory (46080 B, overlaid across phases)
struct ProjSmem {
    float  Ws[2][32][50];     // [half][kk][out+pad]   12800 B
    float2 Xp[2][32][65];     // [half][kk][pair+pad]  33280 B
};
struct ScanSmem { float wsh[16]; float rsh[16]; float km; };
// wsum blocks overlay: float s_twr[1024]; float s_beta[1024];  (8 KB)
// proj epilogue overlay: float2 buf[12][256] (24 KB)

__global__ __launch_bounds__(NTHREADS) void rwkv_persistent(
    const float* __restrict__ x,
    const float* __restrict__ time_w,
    const float* __restrict__ alpha,
    const float* __restrict__ beta,
    const float* __restrict__ gamma,
    const float* __restrict__ Wk, const float* __restrict__ bk,
    const float* __restrict__ Wv, const float* __restrict__ bv,
    const float* __restrict__ Wr, const float* __restrict__ br,
    const float* __restrict__ Wo, const float* __restrict__ bo,
    float* __restrict__ out)
{
    __shared__ __align__(16) char s_raw[sizeof(ProjSmem)];
    int bid = blockIdx.x;
    int tid = threadIdx.x;

    // ======================= PHASE A =======================
    if (bid < 128) {
        // ---- projection partial GEMM ----
        ProjSmem* S = (ProjSmem*)s_raw;
        int tile  = bid >> 2;            // 0..31
        int split = bid & 3;             // 0..3
        int row0  = tile * 128;
        int half  = tid >> 8;            // 0..1 : K sub-chunk (64 wide)
        int ht    = tid & 255;
        int rx    = ht & 31;             // pairs rx, rx+32
        int oy    = ht >> 5;             // 0..7
        int o0    = oy * 6;
        int kbaseh = split * 128 + half * 64;
        bool shifted = (kbaseh < CH/2);  // 32-chunks never straddle 256

        ull acc[6][2];
        #pragma unroll
        for (int j = 0; j < 6; j++) { acc[j][0] = 0ull; acc[j][1] = 0ull; }

        for (int kt = 0; kt < 2; kt++) {
            int kc = kbaseh + kt * 32;

            // stage weights: float2 loads (48x32 per half -> 768 f2, 3 rounds)
            #pragma unroll
            for (int it = 0; it < 3; it++) {
                int p   = ht + it * 256;
                int kk2 = p & 15;        // column pair
                int o   = p >> 4;        // 0..47
                const float* wsrc = (o < 16) ? (Wk + o * CH)
                                  : (o < 32) ? (Wv + (o - 16) * CH)
                                             : (Wr + (o - 32) * CH);
                float2 w = *(const float2*)&wsrc[kc + kk2 * 2];
                S->Ws[half][kk2 * 2    ][o] = w.x;
                S->Ws[half][kk2 * 2 + 1][o] = w.y;
            }
            // stage x pairs: float2 loads cross-assembled (1024 tasks, 4 rounds)
            #pragma unroll
            for (int it = 0; it < 4; it++) {
                int p   = ht + it * 256;
                int kk2 = p & 15;        // column pair
                int rp  = p >> 4;        // 0..63
                int c   = kc + kk2 * 2;
                int row = row0 + rp * 2;
                float2 a, b;
                if (shifted) {
                    int t0 = row & (TLEN - 1);
                    a = t0 ? *(const float2*)&x[(row - 1) * CH + c]
                           : make_float2(0.f, 0.f);
                    b = *(const float2*)&x[row * CH + c];
                } else {
                    a = *(const float2*)&x[row * CH + c];
                    b = *(const float2*)&x[(row + 1) * CH + c];
                }
                S->Xp[half][kk2 * 2    ][rp] = make_float2(a.x, b.x);
                S->Xp[half][kk2 * 2 + 1][rp] = make_float2(a.y, b.y);
            }
            __syncthreads();

            #pragma unroll 8
            for (int kk = 0; kk < 32; kk++) {
                ull xv0 = *(const ull*)&S->Xp[half][kk][rx];
                ull xv1 = *(const ull*)&S->Xp[half][kk][rx + 32];
                uint2 w01 = *(const uint2*)&S->Ws[half][kk][o0];
                uint2 w23 = *(const uint2*)&S->Ws[half][kk][o0 + 2];
                uint2 w45 = *(const uint2*)&S->Ws[half][kk][o0 + 4];
                ull wp[6];
                wp[0] = dup2(w01.x); wp[1] = dup2(w01.y);
                wp[2] = dup2(w23.x); wp[3] = dup2(w23.y);
                wp[4] = dup2(w45.x); wp[5] = dup2(w45.y);
                #pragma unroll
                for (int j = 0; j < 6; j++) {
                    ffma2(acc[j][0], wp[j], xv0);
                    ffma2(acc[j][1], wp[j], xv1);
                }
            }
            __syncthreads();
        }

        // epilogue: merge halves via smem, then write [split][d][row]
        float2* buf = (float2*)s_raw;    // [12][256]
        if (half == 1) {
            #pragma unroll
            for (int j = 0; j < 6; j++)
                #pragma unroll
                for (int i = 0; i < 2; i++)
                    buf[(j * 2 + i) * 256 + ht] = *(float2*)&acc[j][i];
        }
        __syncthreads();
        if (half == 0) {
            #pragma unroll
            for (int j = 0; j < 6; j++) {
                int o     = o0 + j;
                int d     = o & 15;
                int which = o >> 4;
                float* dst = (which == 0) ? g_pk : (which == 1) ? g_pv : g_pr;
                dst += (split * DH + d) * NROWS;
                #pragma unroll
                for (int i = 0; i < 2; i++) {
                    float2 b2 = buf[(j * 2 + i) * 256 + ht];
                    float2 a2 = *(float2*)&acc[j][i];
                    a2.x += b2.x; a2.y += b2.y;
                    *(float2*)&dst[row0 + (rx + 32 * i) * 2] = a2;
                }
            }
        }
    } else {
        // ---- wsum on blocks 128..147, smem-staged (LDS inner loop) ----
        float* s_twr  = (float*)s_raw;          // [1024] time_w reversed
        float* s_beta = ((float*)s_raw) + TLEN; // [1024]
        for (int i = tid; i < TLEN; i += NTHREADS) {
            s_twr[i]  = time_w[TLEN - 1 - i];
            s_beta[i] = beta[i];
        }
        __syncthreads();

        int wb   = bid - 128;           // 0..19
        int wid  = tid >> 5;            // 0..15
        int lane = tid & 31;
        for (int u = wb * 16 + wid; u < TLEN; u += 320) {
            float s = 0.f;
            int dmax = TLEN - 1 - u;
            #pragma unroll 4
            for (int d = lane; d <= dmax; d += 32)
                s += s_twr[d] * s_beta[u + d];
            #pragma unroll
            for (int off = 16; off > 0; off >>= 1)
                s += __shfl_down_sync(0xFFFFFFFFu, s, off);
            if (lane == 0) g_wsum[u] = alpha[u] * s;
        }
    }

    grid_barrier(0);

    // ======================= PHASE B : scan (blocks 0..63) =======================
    if (bid < BATCH * DH) {
        ScanSmem* S = (ScanSmem*)s_raw;
        int b = bid >> 4;
        int d = bid & 15;
        int lane = tid & 31;
        int wid  = tid >> 5;            // 0..15
        int t0   = tid * 2;
        int base = d * NROWS + (b << 10) + t0;

        float2 ks = make_float2(0.f, 0.f);
        float2 vs = ks, rs = ks;
        #pragma unroll
        for (int s = 0; s < NSPL; s++) {
            int off = s * (DH * NROWS) + base;
            float2 a = *(const float2*)&g_pk[off];
            float2 c = *(const float2*)&g_pv[off];
            float2 e = *(const float2*)&g_pr[off];
            ks.x += a.x; ks.y += a.y;
            vs.x += c.x; vs.y += c.y;
            rs.x += e.x; rs.y += e.y;
        }
        float bkd = bk[d], bvd = bv[d], brd = br[d];
        float k0 = expf(fminf(fmaxf(ks.x + bkd, -60.f), 30.f));
        float k1 = expf(fminf(fmaxf(ks.y + bkd, -60.f), 30.f));
        float v0 = vs.x + bvd, v1 = vs.y + bvd;
        float r0 = rs.x + brd, r1 = rs.y + brd;

        // local inclusive prefix
        float p0 = k0, p1 = k0 + k1;
        float tot = p1;
        // warp inclusive scan of tot
        float sc = tot;
        #pragma unroll
        for (int off = 1; off < 32; off <<= 1) {
            float n = __shfl_up_sync(0xFFFFFFFFu, sc, off);
            if (lane >= off) sc += n;
        }
        if (lane == 31) S->wsh[wid] = sc;
        // kv reduction
        float kvs = k0 * v0 + k1 * v1;
        #pragma unroll
        for (int off = 16; off > 0; off >>= 1)
            kvs += __shfl_down_sync(0xFFFFFFFFu, kvs, off);
        if (lane == 0) S->rsh[wid] = kvs;
        __syncthreads();
        if (tid == 0) {
            float run = 0.f, kmacc = 0.f;
            #pragma unroll
            for (int w = 0; w < 16; w++) {
                float t = S->wsh[w]; S->wsh[w] = run; run += t;
                kmacc += S->rsh[w];
            }
            S->km = kmacc * (1.0f / (float)TLEN);
        }
        __syncthreads();
        float blk_excl = S->wsh[wid] + (sc - tot);
        float km = S->km;
        float2 wst = *(const float2*)&g_wsum[t0];

        float c0 = blk_excl + p0, c1 = blk_excl + p1;
        float2 o2;
        o2.x = r0 * wst.x * km * __fdividef(1.0f, c0 + 1e-8f);
        o2.y = r1 * wst.y * km * __fdividef(1.0f, c1 + 1e-8f);
        *(float2*)&g_rwkvT[base] = o2;
    }

    grid_barrier(1);

    // ======================= PHASE C : output GEMM =======================
    {
        int o  = tid & 63;
        int rl = tid >> 6;              // 0..7
        const float4* wop = (const float4*)(Wo + o * DH);
        float4 w0 = wop[0], w1 = wop[1], w2 = wop[2], w3 = wop[3];
        float wor[16] = {w0.x,w0.y,w0.z,w0.w, w1.x,w1.y,w1.z,w1.w,
                         w2.x,w2.y,w2.z,w2.w, w3.x,w3.y,w3.z,w3.w};
        float bov = bo[o];

        for (int g = bid; g < NROWS / 8; g += NBLOCKS) {
            int row = g * 8 + rl;
            int t   = row & (TLEN - 1);
            float acc = 0.f;
            #pragma unroll
            for (int d = 0; d < DH; d++)
                acc += __ldg(&g_rwkvT[d * NROWS + row]) * wor[d];
            out[row * OCH + o] = (acc + bov) * gamma[t];
        }
    }
}

// ---------------------------------------------------------------------------
extern "C" void kernel_launch(void* const* d_in, const int* in_sizes, int n_in,
                              void* d_out, int out_size)
{
    const float* x      = (const float*)d_in[0];
    const float* time_w = (const float*)d_in[1];
    const float* alpha  = (const float*)d_in[2];
    const float* beta   = (const float*)d_in[3];
    const float* gamma  = (const float*)d_in[4];
    const float* Wk     = (const float*)d_in[5];
    const float* bk     = (const float*)d_in[6];
    const float* Wv     = (const float*)d_in[7];
    const float* bv     = (const float*)d_in[8];
    const float* Wr     = (const float*)d_in[9];
    const float* br     = (const float*)d_in[10];
    const float* Wo     = (const float*)d_in[11];
    const float* bo     = (const float*)d_in[12];
    float* out = (float*)d_out;

    rwkv_persistent<<<NBLOCKS, NTHREADS>>>(
        x, time_w, alpha, beta, gamma,
        Wk, bk, Wv, bv, Wr, br, Wo, bo, out);
}

// round 17
// speedup vs baseline: 1.2557x; 1.1345x over previous
#include <cuda_runtime.h>
#include <math.h>

// Problem constants (fixed shapes)
#define BATCH 4
#define TLEN  1024
#define CH    512
#define DH    16
#define NROWS (BATCH*TLEN)   // 4096
#define OUTS  48             // k(16) | v(16) | r(16)
#define OCH   64
#define NSPL  4              // K-splits after in-block half merge
#define NBLOCKS 148
#define NTHREADS 512

typedef unsigned long long ull;
typedef unsigned int uint;

// Scratch (device globals)
__device__ float g_pk[NSPL*DH*NROWS];
__device__ float g_pv[NSPL*DH*NROWS];
__device__ float g_pr[NSPL*DH*NROWS];
__device__ float g_rwkvT[DH*NROWS];       // [d][row]
__device__ float g_wsum[TLEN];
__device__ unsigned int g_barcnt[2];      // monotonic barrier counters

__device__ __forceinline__ void ffma2(ull& acc, ull a, ull b) {
    asm("fma.rn.f32x2 %0, %1, %2, %0;" : "+l"(acc) : "l"(a), "l"(b));
}
__device__ __forceinline__ ull dup2(uint w) {
    ull r; asm("mov.b64 %0, {%1, %1};" : "=l"(r) : "r"(w)); return r;
}

// Replay-safe grid barrier (monotonic counter, wrap-safe compare).
__device__ __forceinline__ void grid_barrier(int id) {
    __syncthreads();
    if (threadIdx.x == 0) {
        __threadfence();
        unsigned int ticket = atomicAdd(&g_barcnt[id], 1u);
        unsigned int target = (ticket / NBLOCKS + 1u) * NBLOCKS;
        volatile unsigned int* p = &g_barcnt[id];
        while ((int)(*p - target) < 0) { }
        __threadfence();
    }
    __syncthreads();
}

// Shared memory (46080 B, overlaid across phases)
struct ProjSmem {
    float  Ws[2][32][50];     // [half][kk][out+pad]   12800 B
    float2 Xp[2][32][65];     // [half][kk][pair+pad]  33280 B
};
struct ScanSmem { float wsh[16]; float rsh[16]; float km; };
// wsum blocks overlay: float s_twr[1024]; float s_beta[1024];  (8 KB)
// proj epilogue overlay: float2 buf[12][256] (24 KB)

__global__ __launch_bounds__(NTHREADS) void rwkv_persistent(
    const float* __restrict__ x,
    const float* __restrict__ time_w,
    const float* __restrict__ alpha,
    const float* __restrict__ beta,
    const float* __restrict__ gamma,
    const float* __restrict__ Wk, const float* __restrict__ bk,
    const float* __restrict__ Wv, const float* __restrict__ bv,
    const float* __restrict__ Wr, const float* __restrict__ br,
    const float* __restrict__ Wo, const float* __restrict__ bo,
    float* __restrict__ out)
{
    __shared__ __align__(16) char s_raw[sizeof(ProjSmem)];
    int bid = blockIdx.x;
    int tid = threadIdx.x;

    // ======================= PHASE A =======================
    if (bid < 128) {
        // ---- projection partial GEMM ----
        ProjSmem* S = (ProjSmem*)s_raw;
        int tile  = bid >> 2;            // 0..31
        int split = bid & 3;             // 0..3
        int row0  = tile * 128;
        int half  = tid >> 8;            // 0..1 : K sub-chunk (64 wide)
        int ht    = tid & 255;
        int rx    = ht & 31;             // pairs rx, rx+32
        int oy    = ht >> 5;             // 0..7
        int o0    = oy * 6;
        int kbaseh = split * 128 + half * 64;
        bool shifted = (kbaseh < CH/2);  // 64-chunks never straddle 256

        ull acc[6][2];
        #pragma unroll
        for (int j = 0; j < 6; j++) { acc[j][0] = 0ull; acc[j][1] = 0ull; }

        // ---- register prefetch of BOTH K-stages (14 LDG.64, one window) ----
        float2 wreg[2][3];
        float2 areg[2][4], breg[2][4];
        #pragma unroll
        for (int kt = 0; kt < 2; kt++) {
            int kc = kbaseh + kt * 32;
            #pragma unroll
            for (int it = 0; it < 3; it++) {
                int p   = ht + it * 256;
                int kk2 = p & 15;
                int o   = p >> 4;        // 0..47
                const float* wsrc = (o < 16) ? (Wk + o * CH)
                                  : (o < 32) ? (Wv + (o - 16) * CH)
                                             : (Wr + (o - 32) * CH);
                wreg[kt][it] = *(const float2*)&wsrc[kc + kk2 * 2];
            }
            #pragma unroll
            for (int it = 0; it < 4; it++) {
                int p   = ht + it * 256;
                int kk2 = p & 15;
                int rp  = p >> 4;        // 0..63
                int c   = kc + kk2 * 2;
                int row = row0 + rp * 2;
                if (shifted) {
                    int t0 = row & (TLEN - 1);
                    areg[kt][it] = t0 ? *(const float2*)&x[(row - 1) * CH + c]
                                      : make_float2(0.f, 0.f);
                    breg[kt][it] = *(const float2*)&x[row * CH + c];
                } else {
                    areg[kt][it] = *(const float2*)&x[row * CH + c];
                    breg[kt][it] = *(const float2*)&x[(row + 1) * CH + c];
                }
            }
        }

        #pragma unroll
        for (int kt = 0; kt < 2; kt++) {
            // store stage kt to smem (stage-1 stores wait behind compute-0 sync)
            #pragma unroll
            for (int it = 0; it < 3; it++) {
                int p   = ht + it * 256;
                int kk2 = p & 15;
                int o   = p >> 4;
                S->Ws[half][kk2 * 2    ][o] = wreg[kt][it].x;
                S->Ws[half][kk2 * 2 + 1][o] = wreg[kt][it].y;
            }
            #pragma unroll
            for (int it = 0; it < 4; it++) {
                int p   = ht + it * 256;
                int kk2 = p & 15;
                int rp  = p >> 4;
                S->Xp[half][kk2 * 2    ][rp] =
                    make_float2(areg[kt][it].x, breg[kt][it].x);
                S->Xp[half][kk2 * 2 + 1][rp] =
                    make_float2(areg[kt][it].y, breg[kt][it].y);
            }
            __syncthreads();

            #pragma unroll 8
            for (int kk = 0; kk < 32; kk++) {
                ull xv0 = *(const ull*)&S->Xp[half][kk][rx];
                ull xv1 = *(const ull*)&S->Xp[half][kk][rx + 32];
                uint2 w01 = *(const uint2*)&S->Ws[half][kk][o0];
                uint2 w23 = *(const uint2*)&S->Ws[half][kk][o0 + 2];
                uint2 w45 = *(const uint2*)&S->Ws[half][kk][o0 + 4];
                ull wp[6];
                wp[0] = dup2(w01.x); wp[1] = dup2(w01.y);
                wp[2] = dup2(w23.x); wp[3] = dup2(w23.y);
                wp[4] = dup2(w45.x); wp[5] = dup2(w45.y);
                #pragma unroll
                for (int j = 0; j < 6; j++) {
                    ffma2(acc[j][0], wp[j], xv0);
                    ffma2(acc[j][1], wp[j], xv1);
                }
            }
            __syncthreads();
        }

        // epilogue: merge halves via smem, then write [split][d][row]
        float2* buf = (float2*)s_raw;    // [12][256]
        if (half == 1) {
            #pragma unroll
            for (int j = 0; j < 6; j++)
                #pragma unroll
                for (int i = 0; i < 2; i++)
                    buf[(j * 2 + i) * 256 + ht] = *(float2*)&acc[j][i];
        }
        __syncthreads();
        if (half == 0) {
            #pragma unroll
            for (int j = 0; j < 6; j++) {
                int o     = o0 + j;
                int d     = o & 15;
                int which = o >> 4;
                float* dst = (which == 0) ? g_pk : (which == 1) ? g_pv : g_pr;
                dst += (split * DH + d) * NROWS;
                #pragma unroll
                for (int i = 0; i < 2; i++) {
                    float2 b2 = buf[(j * 2 + i) * 256 + ht];
                    float2 a2 = *(float2*)&acc[j][i];
                    a2.x += b2.x; a2.y += b2.y;
                    *(float2*)&dst[row0 + (rx + 32 * i) * 2] = a2;
                }
            }
        }
    } else {
        // ---- wsum on blocks 128..147, smem-staged (LDS inner loop) ----
        float* s_twr  = (float*)s_raw;          // [1024] time_w reversed
        float* s_beta = ((float*)s_raw) + TLEN; // [1024]
        for (int i = tid; i < TLEN; i += NTHREADS) {
            s_twr[i]  = time_w[TLEN - 1 - i];
            s_beta[i] = beta[i];
        }
        __syncthreads();

        int wb   = bid - 128;           // 0..19
        int wid  = tid >> 5;            // 0..15
        int lane = tid & 31;
        for (int u = wb * 16 + wid; u < TLEN; u += 320) {
            float s = 0.f;
            int dmax = TLEN - 1 - u;
            #pragma unroll 4
            for (int d = lane; d <= dmax; d += 32)
                s += s_twr[d] * s_beta[u + d];
            #pragma unroll
            for (int off = 16; off > 0; off >>= 1)
                s += __shfl_down_sync(0xFFFFFFFFu, s, off);
            if (lane == 0) g_wsum[u] = alpha[u] * s;
        }
    }

    grid_barrier(0);

    // ======================= PHASE B : scan (blocks 0..63) =======================
    if (bid < BATCH * DH) {
        ScanSmem* S = (ScanSmem*)s_raw;
        int b = bid >> 4;
        int d = bid & 15;
        int lane = tid & 31;
        int wid  = tid >> 5;            // 0..15
        int t0   = tid * 2;
        int base = d * NROWS + (b << 10) + t0;

        float2 ks = make_float2(0.f, 0.f);
        float2 vs = ks, rs = ks;
        #pragma unroll
        for (int s = 0; s < NSPL; s++) {
            int off = s * (DH * NROWS) + base;
            float2 a = *(const float2*)&g_pk[off];
            float2 c = *(const float2*)&g_pv[off];
            float2 e = *(const float2*)&g_pr[off];
            ks.x += a.x; ks.y += a.y;
            vs.x += c.x; vs.y += c.y;
            rs.x += e.x; rs.y += e.y;
        }
        float bkd = bk[d], bvd = bv[d], brd = br[d];
        float k0 = expf(fminf(fmaxf(ks.x + bkd, -60.f), 30.f));
        float k1 = expf(fminf(fmaxf(ks.y + bkd, -60.f), 30.f));
        float v0 = vs.x + bvd, v1 = vs.y + bvd;
        float r0 = rs.x + brd, r1 = rs.y + brd;

        // local inclusive prefix
        float p0 = k0, p1 = k0 + k1;
        float tot = p1;
        // warp inclusive scan of tot
        float sc = tot;
        #pragma unroll
        for (int off = 1; off < 32; off <<= 1) {
            float n = __shfl_up_sync(0xFFFFFFFFu, sc, off);
            if (lane >= off) sc += n;
        }
        if (lane == 31) S->wsh[wid] = sc;
        // kv reduction
        float kvs = k0 * v0 + k1 * v1;
        #pragma unroll
        for (int off = 16; off > 0; off >>= 1)
            kvs += __shfl_down_sync(0xFFFFFFFFu, kvs, off);
        if (lane == 0) S->rsh[wid] = kvs;
        __syncthreads();
        if (tid == 0) {
            float run = 0.f, kmacc = 0.f;
            #pragma unroll
            for (int w = 0; w < 16; w++) {
                float t = S->wsh[w]; S->wsh[w] = run; run += t;
                kmacc += S->rsh[w];
            }
            S->km = kmacc * (1.0f / (float)TLEN);
        }
        __syncthreads();
        float blk_excl = S->wsh[wid] + (sc - tot);
        float km = S->km;
        float2 wst = *(const float2*)&g_wsum[t0];

        float c0 = blk_excl + p0, c1 = blk_excl + p1;
        float2 o2;
        o2.x = r0 * wst.x * km * __fdividef(1.0f, c0 + 1e-8f);
        o2.y = r1 * wst.y * km * __fdividef(1.0f, c1 + 1e-8f);
        *(float2*)&g_rwkvT[base] = o2;
    }

    grid_barrier(1);

    // ======================= PHASE C : output GEMM =======================
    {
        int o  = tid & 63;
        int rl = tid >> 6;              // 0..7
        const float4* wop = (const float4*)(Wo + o * DH);
        float4 w0 = wop[0], w1 = wop[1], w2 = wop[2], w3 = wop[3];
        float wor[16] = {w0.x,w0.y,w0.z,w0.w, w1.x,w1.y,w1.z,w1.w,
                         w2.x,w2.y,w2.z,w2.w, w3.x,w3.y,w3.z,w3.w};
        float bov = bo[o];

        for (int g = bid; g < NROWS / 8; g += NBLOCKS) {
            int row = g * 8 + rl;
            int t   = row & (TLEN - 1);
            float acc = 0.f;
            #pragma unroll
            for (int d = 0; d < DH; d++)
                acc += __ldg(&g_rwkvT[d * NROWS + row]) * wor[d];
            out[row * OCH + o] = (acc + bov) * gamma[t];
        }
    }
}

// ---------------------------------------------------------------------------
extern "C" void kernel_launch(void* const* d_in, const int* in_sizes, int n_in,
                              void* d_out, int out_size)
{
    const float* x      = (const float*)d_in[0];
    const float* time_w = (const float*)d_in[1];
    const float* alpha  = (const float*)d_in[2];
    const float* beta   = (const float*)d_in[3];
    const float* gamma  = (const float*)d_in[4];
    const float* Wk     = (const float*)d_in[5];
    const float* bk     = (const float*)d_in[6];
    const float* Wv     = (const float*)d_in[7];
    const float* bv     = (const float*)d_in[8];
    const float* Wr     = (const float*)d_in[9];
    const float* br     = (const float*)d_in[10];
    const float* Wo     = (const float*)d_in[11];
    const float* bo     = (const float*)d_in[12];
    float* out = (float*)d_out;

    rwkv_persistent<<<NBLOCKS, NTHREADS>>>(
        x, time_w, alpha, beta, gamma,
        Wk, bk, Wv, bv, Wr, br, Wo, bo, out);
}